// round 17
// baseline (speedup 1.0000x reference)
#include <cuda_runtime.h>
#include <math.h>

// Problem constants
#define Vv 32000
#define Ee 512
#define Hh 512
#define G4 2048   // 4*H
#define Bb 64
#define Tt 256
#define GRID 128  // persistent CTAs, 1/SM -> all co-resident
#define NT 512    // 16 warps/CTA -> 4 warps/SMSP

typedef unsigned long long ull;

// ---------------- device scratch ----------------
__device__ float g_WT_fc[(size_t)Ee * Vv];   // [k][v] transposed W_fc
__device__ float g_h[2][2][Hh * Bb];         // [ping][layer][unit*64+b]
__device__ ull   g_amax[Bb];                 // packed (orderable float | ~idx)
__device__ unsigned g_bar_count;
__device__ volatile unsigned g_bar_gen;

// ---------------- packed f32x2 FMA helpers ----------------
__device__ __forceinline__ void ffma2(ull& d, ull a, ull b) {
    asm("fma.rn.f32x2 %0, %1, %2, %0;" : "+l"(d) : "l"(a), "l"(b));
}
__device__ __forceinline__ ull pack2(float v) {
    ull r; asm("mov.b64 %0, {%1, %1};" : "=l"(r) : "f"(v)); return r;
}
__device__ __forceinline__ float2 unpack2(ull a) {
    float2 r; asm("mov.b64 {%0, %1}, %2;" : "=f"(r.x), "=f"(r.y) : "l"(a)); return r;
}
__device__ __forceinline__ ull amax_pack(float f, int idx) {
    unsigned b = __float_as_uint(f);
    unsigned key = (b & 0x80000000u) ? ~b : (b | 0x80000000u);
    return ((ull)key << 32) | (ull)(0xFFFFFFFFu - (unsigned)idx);
}

// ---------------- grid-wide barrier ----------------
__device__ __forceinline__ void gsync() {
    __threadfence();
    __syncthreads();
    if (threadIdx.x == 0) {
        unsigned gen = g_bar_gen;
        unsigned t = atomicAdd(&g_bar_count, 1u);
        if (t == GRID - 1) {
            g_bar_count = 0;
            __threadfence();
            g_bar_gen = gen + 1;
        } else {
            while (g_bar_gen == gen) { }
        }
    }
    __syncthreads();
}

// smem map (floats): [0, 32768) gate weights; [32768, 49152) scratch (64 KB)
#define STG_OFF 32768

// 16 ffma2 for one k: 2 units (w0,w1 rows) x 4 gates x 2 b-pairs
#define GATE_K(AV, KABS) { \
    float4 w0 = *(const float4*)(w0p + (KABS) * 4); \
    float4 w1 = *(const float4*)(w1p + (KABS) * 4); \
    ffma2(acc[0],  AV.x, pack2(w0.x)); ffma2(acc[1],  AV.y, pack2(w0.x)); \
    ffma2(acc[2],  AV.x, pack2(w0.y)); ffma2(acc[3],  AV.y, pack2(w0.y)); \
    ffma2(acc[4],  AV.x, pack2(w0.z)); ffma2(acc[5],  AV.y, pack2(w0.z)); \
    ffma2(acc[6],  AV.x, pack2(w0.w)); ffma2(acc[7],  AV.y, pack2(w0.w)); \
    ffma2(acc[8],  AV.x, pack2(w1.x)); ffma2(acc[9],  AV.y, pack2(w1.x)); \
    ffma2(acc[10], AV.x, pack2(w1.y)); ffma2(acc[11], AV.y, pack2(w1.y)); \
    ffma2(acc[12], AV.x, pack2(w1.z)); ffma2(acc[13], AV.y, pack2(w1.z)); \
    ffma2(acc[14], AV.x, pack2(w1.w)); ffma2(acc[15], AV.y, pack2(w1.w)); }

// ---------------- gate reduction (16 partials) + cell update ----------------
__device__ __forceinline__ void gate_finish(
    float* wsm, ull* acc, float* __restrict__ hout, float& creg,
    const float* __restrict__ bih, const float* __restrict__ bhh,
    int cta, int tid)
{
    ull* sred = (ull*)(wsm + STG_OFF);       // 512 x 16 ull = 64 KB
    #pragma unroll
    for (int i = 0; i < 16; i++) sred[tid * 16 + i] = acc[i];
    __syncthreads();
    if (tid < 256) {
        int u = tid >> 6, b = tid & 63;
        int jgc = u >> 1, uu = u & 1;
        int bqc = b >> 2, bp = (b >> 1) & 1, be = b & 1;
        int lanec = jgc * 16 + bqc;
        float gate[4];
        #pragma unroll
        for (int g = 0; g < 4; g++) {
            float s = 0.0f;
            #pragma unroll
            for (int ww = 0; ww < 16; ww++) {
                float2 p = unpack2(sred[(ww * 32 + lanec) * 16 + uu * 8 + g * 2 + bp]);
                s += be ? p.y : p.x;
            }
            gate[g] = s;
        }
        int j0 = cta * 4 + u;
        float iv = gate[0] + bih[j0]        + bhh[j0];
        float fv = gate[1] + bih[512 + j0]  + bhh[512 + j0];
        float gv = gate[2] + bih[1024 + j0] + bhh[1024 + j0];
        float ov = gate[3] + bih[1536 + j0] + bhh[1536 + j0];
        float ig = 1.0f / (1.0f + expf(-iv));
        float fg = 1.0f / (1.0f + expf(-fv));
        float og = 1.0f / (1.0f + expf(-ov));
        float cn = fg * creg + ig * tanhf(gv);
        float hn = og * tanhf(cn);
        creg = cn;
        __stcg(&hout[j0 * Bb + b], hn);
    }
    __syncthreads();
}

// ---------------- layer 0: x gathered from emb (staged), h direct ----------
__device__ __forceinline__ void lstm_layer0(
    float* wsm, const float* __restrict__ emb, const int* __restrict__ s_tok,
    const float* __restrict__ hin, float* __restrict__ hout, float& creg,
    const float* __restrict__ bih, const float* __restrict__ bhh,
    int cta, int tid)
{
    float* stg = wsm + STG_OFF;              // 2 bufs x 2048 floats
    int w = tid >> 5, lane = tid & 31;
    int m = w >> 3, ks = w & 7;
    int jg = lane >> 4, bq = lane & 15;
    int gb = tid >> 3, kq = tid & 7;         // gather: 64 rows x 8 thr x 4 floats

    ull acc[16];
    #pragma unroll
    for (int i = 0; i < 16; i++) acc[i] = 0ull;

    const float* w0p = wsm + (unsigned)(m * 4 + jg * 2) * 2048;
    const float* w1p = w0p + 2048;
    const float* erow = emb + (size_t)s_tok[gb] * Ee;

    {   // stage chunk 0
        float4 q = __ldcg((const float4*)(erow + kq * 4));
        stg[(kq * 4 + 0) * 64 + gb] = q.x; stg[(kq * 4 + 1) * 64 + gb] = q.y;
        stg[(kq * 4 + 2) * 64 + gb] = q.z; stg[(kq * 4 + 3) * 64 + gb] = q.w;
    }
    __syncthreads();
    int d = 0;
    #pragma unroll 1
    for (int c = 0; c < 16; c++) {
        float4 q;
        if (c < 15) q = __ldcg((const float4*)(erow + (c + 1) * 32 + kq * 4));
        #pragma unroll
        for (int j = 0; j < 4; j++) {
            int kin = ks * 4 + j;
            int kabs = c * 32 + kin;
            ulonglong2 av;
            if (m == 0)
                av = *(const ulonglong2*)(stg + d * 2048 + kin * 64 + bq * 4);
            else
                av = __ldcg((const ulonglong2*)(hin + kabs * 64 + bq * 4));
            GATE_K(av, kabs);
        }
        if (c < 15) {
            float* nb = stg + (d ^ 1) * 2048;
            nb[(kq * 4 + 0) * 64 + gb] = q.x; nb[(kq * 4 + 1) * 64 + gb] = q.y;
            nb[(kq * 4 + 2) * 64 + gb] = q.z; nb[(kq * 4 + 3) * 64 + gb] = q.w;
        }
        __syncthreads();
        d ^= 1;
    }
    gate_finish(wsm, acc, hout, creg, bih, bhh, cta, tid);
}

// ---------------- layer 1: both inputs direct LDG, sync-free mainloop ------
__device__ __forceinline__ void lstm_layer1(
    float* wsm, const float* __restrict__ inp, const float* __restrict__ hin,
    float* __restrict__ hout, float& creg,
    const float* __restrict__ bih, const float* __restrict__ bhh,
    int cta, int tid)
{
    int w = tid >> 5, lane = tid & 31;
    int m = w >> 3, ks = w & 7;
    int jg = lane >> 4, bq = lane & 15;

    ull acc[16];
    #pragma unroll
    for (int i = 0; i < 16; i++) acc[i] = 0ull;

    const float* w0p = wsm + (unsigned)(8 + m * 4 + jg * 2) * 2048;
    const float* w1p = w0p + 2048;
    const float* ap = (m ? hin : inp) + bq * 4;
    int k0 = ks * 64;

    ulonglong2 A[4], B[4];
    #pragma unroll
    for (int j = 0; j < 4; j++)
        A[j] = __ldcg((const ulonglong2*)(ap + (k0 + j) * 64));
    #pragma unroll 1
    for (int g = 0; g < 16; g++) {
        if (g < 15) {
            #pragma unroll
            for (int j = 0; j < 4; j++)
                B[j] = __ldcg((const ulonglong2*)(ap + (k0 + g * 4 + 4 + j) * 64));
        }
        #pragma unroll
        for (int j = 0; j < 4; j++) {
            int kabs = k0 + g * 4 + j;
            GATE_K(A[j], kabs);
        }
        #pragma unroll
        for (int j = 0; j < 4; j++) A[j] = B[j];
    }
    gate_finish(wsm, acc, hout, creg, bih, bhh, cta, tid);
}

// ---------------- single persistent kernel ----------------
__global__ void __launch_bounds__(NT, 1)
kmain(const int* __restrict__ x, const float* __restrict__ emb,
      const float* __restrict__ W_ih, const float* __restrict__ W_hh,
      const float* __restrict__ b_ih, const float* __restrict__ b_hh,
      const float* __restrict__ W_fc, const float* __restrict__ bfc,
      float* __restrict__ out)
{
    extern __shared__ float wsm[];
    __shared__ int s_tok[64];
    __shared__ ull s_fc[16][8];

    int tid = threadIdx.x;
    int cta = blockIdx.x;

    // ================= per-replay init =================
    ((float2*)&g_h[0][0][0])[cta * NT + tid] = make_float2(0.0f, 0.0f);
    if (cta == 0 && tid < Bb)
        g_amax[tid] = amax_pack(0.0f, x[tid * Tt]);   // seed step-0 tokens

    // gate weights -> smem: row r = layer*8 + m*4 + u; wsm[r][k] = (wi,wf,wg,wo)
    #pragma unroll 1
    for (int r = 0; r < 16; r++) {
        int l = r >> 3, m = (r >> 2) & 1, u = r & 3;
        const float* base = (m ? W_hh : W_ih) + (size_t)l * G4 * 512
                            + (size_t)(cta * 4 + u) * 512;
        int k = tid;                         // 0..511
        float4 wv;
        wv.x = base[k];
        wv.y = base[(size_t)512 * 512 + k];
        wv.z = base[(size_t)1024 * 512 + k];
        wv.w = base[(size_t)1536 * 512 + k];
        *(float4*)&wsm[r * 2048 + k * 4] = wv;
    }
    // transpose W_fc -> g_WT_fc [k][v]: 250 v per CTA, 2 threads per v
    if (tid < 500) {
        int v = cta * 250 + (tid >> 1);
        int h0 = (tid & 1) * 64;
        const float4* src = (const float4*)(W_fc + (size_t)v * Ee);
        #pragma unroll 4
        for (int kq = h0; kq < h0 + 64; kq++) {
            float4 r = src[kq];
            size_t k = (size_t)kq * 4;
            g_WT_fc[k * Vv + v]       = r.x;
            g_WT_fc[(k + 1) * Vv + v] = r.y;
            g_WT_fc[(k + 2) * Vv + v] = r.z;
            g_WT_fc[(k + 3) * Vv + v] = r.w;
        }
    }

    float creg0 = 0.0f, creg1 = 0.0f;
    gsync();

    // ================= timestep loop =================
    for (int t = 0; t < Tt; t++) {
        int pi = t & 1, po = pi ^ 1;

        // decode this step's tokens (argmax of previous step / seeded x0)
        if (tid < 64) {
            ull pv = __ldcg((const ull*)&g_amax[tid]);
            s_tok[tid] = (int)(0xFFFFFFFFu - (unsigned)(pv & 0xFFFFFFFFull));
        }
        __syncthreads();

        // ---- layer 0
        lstm_layer0(wsm, emb, s_tok, &g_h[pi][0][0], &g_h[po][0][0], creg0,
                    b_ih, b_hh, cta, tid);
        gsync();

        if (cta == 0 && tid < Bb) g_amax[tid] = 0ull;

        // ---- layer 1
        lstm_layer1(wsm, &g_h[po][0][0], &g_h[pi][1][0], &g_h[po][1][0], creg1,
                    b_ih + G4, b_hh + G4, cta, tid);
        gsync();

        // ---- FC head: lane tile 4 vocab x 8 batch, 4-stage pipeline ----
        if (cta < 125) {
            int w = tid >> 5, lane = tid & 31;
            int bq = w & 7, vh = w >> 3;
            int v0 = cta * 256 + vh * 128 + lane * 4;
            const float* hb = &g_h[po][1][0] + bq * 8;
            const float* Wb = g_WT_fc + v0;

            ull acc[4][4];
            #pragma unroll
            for (int v = 0; v < 4; v++) {
                acc[v][0] = 0; acc[v][1] = 0; acc[v][2] = 0; acc[v][3] = 0;
            }

            float4 W0, W1, W2, W3;
            ulonglong2 A0[2], A1[2], A2[2], A3[2];

#define FCLOAD(W, A, kk) { \
    W = __ldcg((const float4*)(Wb + (size_t)(kk) * Vv)); \
    const ulonglong2* ar = (const ulonglong2*)(hb + (size_t)(kk) * Bb); \
    A[0] = __ldcg(ar); A[1] = __ldcg(ar + 1); }

#define FCCOMP(W, A) { \
    ull ap0 = A[0].x, ap1 = A[0].y, ap2 = A[1].x, ap3 = A[1].y; \
    { ull wp = pack2(W.x); ffma2(acc[0][0], ap0, wp); ffma2(acc[0][1], ap1, wp); \
      ffma2(acc[0][2], ap2, wp); ffma2(acc[0][3], ap3, wp); } \
    { ull wp = pack2(W.y); ffma2(acc[1][0], ap0, wp); ffma2(acc[1][1], ap1, wp); \
      ffma2(acc[1][2], ap2, wp); ffma2(acc[1][3], ap3, wp); } \
    { ull wp = pack2(W.z); ffma2(acc[2][0], ap0, wp); ffma2(acc[2][1], ap1, wp); \
      ffma2(acc[2][2], ap2, wp); ffma2(acc[2][3], ap3, wp); } \
    { ull wp = pack2(W.w); ffma2(acc[3][0], ap0, wp); ffma2(acc[3][1], ap1, wp); \
      ffma2(acc[3][2], ap2, wp); ffma2(acc[3][3], ap3, wp); } }

            FCLOAD(W0, A0, 0); FCLOAD(W1, A1, 1);
            FCLOAD(W2, A2, 2); FCLOAD(W3, A3, 3);
            #pragma unroll 1
            for (int k = 0; k < 512; k += 4) {
                FCCOMP(W0, A0); FCLOAD(W0, A0, (k + 4 < 512) ? k + 4 : 0);
                FCCOMP(W1, A1); FCLOAD(W1, A1, (k + 5 < 512) ? k + 5 : 1);
                FCCOMP(W2, A2); FCLOAD(W2, A2, (k + 6 < 512) ? k + 6 : 2);
                FCCOMP(W3, A3); FCLOAD(W3, A3, (k + 7 < 512) ? k + 7 : 3);
            }
#undef FCLOAD
#undef FCCOMP

            float4 bi = __ldcg((const float4*)(bfc + v0));
            float bias[4] = {bi.x, bi.y, bi.z, bi.w};

            if (t == Tt - 1) {
                #pragma unroll
                for (int bb = 0; bb < 8; bb++) {
                    int b = bq * 8 + bb;
                    int p = bb >> 1, hi = bb & 1;
                    float vals[4];
                    #pragma unroll
                    for (int v = 0; v < 4; v++) {
                        float2 t2 = unpack2(acc[v][p]);
                        vals[v] = (hi ? t2.y : t2.x) + bias[v];
                    }
                    *(float4*)(out + (size_t)b * Vv + v0) =
                        make_float4(vals[0], vals[1], vals[2], vals[3]);
                }
            } else {
                #pragma unroll
                for (int bb = 0; bb < 8; bb++) {
                    int p = bb >> 1, hi = bb & 1;
                    float mv; int mi;
                    {
                        float2 t2 = unpack2(acc[0][p]);
                        mv = (hi ? t2.y : t2.x) + bias[0]; mi = v0;
                    }
                    #pragma unroll
                    for (int v = 1; v < 4; v++) {
                        float2 t2 = unpack2(acc[v][p]);
                        float e = (hi ? t2.y : t2.x) + bias[v];
                        if (e > mv) { mv = e; mi = v0 + v; }
                    }
                    ull pk = amax_pack(mv, mi);
                    #pragma unroll
                    for (int o = 16; o > 0; o >>= 1) {
                        ull op = __shfl_down_sync(0xffffffffu, pk, o);
                        if (op > pk) pk = op;
                    }
                    if (lane == 0) s_fc[w][bb] = pk;
                }
                __syncthreads();
                if (tid < 64) {
                    int b = tid;
                    ull p0 = s_fc[b >> 3][b & 7];
                    ull p1 = s_fc[8 + (b >> 3)][b & 7];
                    atomicMax(&g_amax[b], p0 > p1 ? p0 : p1);
                }
            }
        }
        gsync();
    }
}

// ---------------- host driver ----------------
extern "C" void kernel_launch(void* const* d_in, const int* in_sizes, int n_in,
                              void* d_out, int out_size) {
    const int*   x    = (const int*)d_in[0];
    const float* emb  = (const float*)d_in[1];
    const float* W_ih = (const float*)d_in[2];
    const float* W_hh = (const float*)d_in[3];
    const float* b_ih = (const float*)d_in[4];
    const float* b_hh = (const float*)d_in[5];
    const float* W_fc = (const float*)d_in[6];
    const float* b_fc = (const float*)d_in[7];
    float* out = (float*)d_out;

    // 32768 gate-weight floats + 16384 scratch floats = 192 KB
    const int SMEM = (32768 + 16384) * (int)sizeof(float);
    cudaFuncSetAttribute(kmain, cudaFuncAttributeMaxDynamicSharedMemorySize, SMEM);

    kmain<<<GRID, NT, SMEM>>>(x, emb, W_ih, W_hh, b_ih, b_hh, W_fc, b_fc, out);
}